// round 1
// baseline (speedup 1.0000x reference)
#include <cuda_runtime.h>
#include <math.h>

#define T_TOK 8192
#define H_DIM 2048
#define HS_DIM 4096
#define P_DIM 1024
#define NE 8
#define TOPK 2
#define TK (T_TOK*TOPK)

// ---------------- scratch (device globals: allowed alloc mechanism) ----------
__device__ float g_u[(size_t)T_TOK * HS_DIM];     // relu(x @ sg^T)       134 MB
__device__ float g_h1[(size_t)T_TOK * H_DIM];     // shared expert out     67 MB
__device__ float g_act[(size_t)TK * P_DIM];       // permuted expert act   64 MB
__device__ float g_yout[(size_t)TK * H_DIM];      // permuted down out    134 MB
__device__ float g_gate[T_TOK * NE];              // sigmoid gates
__device__ int   g_perm[TK];                      // slot -> token
__device__ int   g_eid[TK];                       // slot -> expert
__device__ float g_cw[TK];                        // slot -> combine weight
__device__ float g_gval[TK];                      // slot -> gate value
__device__ int   g_slot[TK];                      // token*2+k -> slot
__device__ int   g_sel[TK];                       // token*2+k -> expert
__device__ float g_wts[TK];                       // token*2+k -> weight
__device__ int   g_counts[NE];
__device__ int   g_offsets[NE + 1];
__device__ int   g_cursor[NE];
__device__ float g_importance[NE];

// ---------------- small kernels ---------------------------------------------
__global__ void zero_kernel() {
    int i = threadIdx.x;
    if (i < NE) { g_counts[i] = 0; g_cursor[i] = 0; g_importance[i] = 0.f; }
}

// one warp per token: logits, softmax, top2, aux stats
__global__ void router_kernel(const float* __restrict__ x,
                              const float* __restrict__ rw,
                              float* __restrict__ logits_out) {
    __shared__ float s_imp[NE];
    __shared__ int   s_cnt[NE];
    int tid = threadIdx.x;
    if (tid < NE) { s_imp[tid] = 0.f; s_cnt[tid] = 0; }
    __syncthreads();
    int warp = tid >> 5, lane = tid & 31;
    int t = blockIdx.x * 8 + warp;
    float acc[NE];
#pragma unroll
    for (int e = 0; e < NE; e++) acc[e] = 0.f;
    const float* xr = x + (size_t)t * H_DIM;
    for (int i = lane; i < H_DIM; i += 32) {
        float xv = xr[i];
#pragma unroll
        for (int e = 0; e < NE; e++) acc[e] += xv * rw[e * H_DIM + i];
    }
#pragma unroll
    for (int e = 0; e < NE; e++) {
#pragma unroll
        for (int o = 16; o > 0; o >>= 1) acc[e] += __shfl_xor_sync(0xffffffffu, acc[e], o);
    }
    if (lane == 0) {
        float mx = acc[0];
#pragma unroll
        for (int e = 1; e < NE; e++) mx = fmaxf(mx, acc[e]);
        float p[NE]; float s = 0.f;
#pragma unroll
        for (int e = 0; e < NE; e++) { p[e] = expf(acc[e] - mx); s += p[e]; }
        float inv = 1.f / s;
        int i0 = 0; float b0 = -1.f;
#pragma unroll
        for (int e = 0; e < NE; e++) {
            p[e] *= inv;
            logits_out[t * NE + e] = acc[e];
            if (p[e] > b0) { b0 = p[e]; i0 = e; }
        }
        int i1 = 0; float b1 = -1.f;
#pragma unroll
        for (int e = 0; e < NE; e++) {
            if (e != i0 && p[e] > b1) { b1 = p[e]; i1 = e; }
        }
        g_sel[t * 2] = i0; g_sel[t * 2 + 1] = i1;
        g_wts[t * 2] = b0; g_wts[t * 2 + 1] = b1;
#pragma unroll
        for (int e = 0; e < NE; e++) atomicAdd(&s_imp[e], p[e]);
        atomicAdd(&s_cnt[i0], 1); atomicAdd(&s_cnt[i1], 1);
    }
    __syncthreads();
    if (tid < NE) {
        atomicAdd(&g_importance[tid], s_imp[tid]);
        atomicAdd(&g_counts[tid], s_cnt[tid]);
    }
}

__global__ void offsets_kernel() {
    int off = 0;
    for (int e = 0; e < NE; e++) { g_offsets[e] = off; g_cursor[e] = off; off += g_counts[e]; }
    g_offsets[NE] = off;
}

__global__ void scatter_kernel() {
    int t = blockIdx.x * blockDim.x + threadIdx.x;
    if (t >= T_TOK) return;
#pragma unroll
    for (int k = 0; k < 2; k++) {
        int e = g_sel[t * 2 + k];
        int pos = atomicAdd(&g_cursor[e], 1);
        g_perm[pos] = t;
        g_cw[pos] = g_wts[t * 2 + k];
        g_eid[pos] = e;
        g_slot[t * 2 + k] = pos;
    }
}

// one warp per token: g[t,e] = sigmoid(h1[t] . pg_w[e])
__global__ void pg_kernel(const float* __restrict__ h1,
                          const float* __restrict__ pg) {
    int tid = threadIdx.x;
    int warp = tid >> 5, lane = tid & 31;
    int t = blockIdx.x * 8 + warp;
    float acc[NE];
#pragma unroll
    for (int e = 0; e < NE; e++) acc[e] = 0.f;
    const float* hr = h1 + (size_t)t * H_DIM;
    for (int i = lane; i < H_DIM; i += 32) {
        float hv = hr[i];
#pragma unroll
        for (int e = 0; e < NE; e++) acc[e] += hv * pg[e * H_DIM + i];
    }
#pragma unroll
    for (int e = 0; e < NE; e++) {
#pragma unroll
        for (int o = 16; o > 0; o >>= 1) acc[e] += __shfl_xor_sync(0xffffffffu, acc[e], o);
    }
    if (lane < NE) {
        // lane e writes expert e's value: need per-expert value in one lane.
    }
    if (lane == 0) {
#pragma unroll
        for (int e = 0; e < NE; e++)
            g_gate[t * NE + e] = 1.f / (1.f + expf(-acc[e]));
    }
}

__global__ void gval_kernel() {
    int s = blockIdx.x * blockDim.x + threadIdx.x;
    if (s >= TK) return;
    g_gval[s] = g_gate[g_perm[s] * NE + g_eid[s]];
}

// ---------------- fp32 TN GEMM: C[M,N] = A[M,K] @ B[N,K]^T ------------------
// 128x128 tile, BK=16, 256 threads, 8x8 per-thread microtile.

template<int EPI> // 0 none, 1 relu
__global__ void __launch_bounds__(256) gemm_tn_plain(const float* __restrict__ A,
                                                     const float* __restrict__ B,
                                                     float* __restrict__ C,
                                                     int N, int K) {
    const int BM = 128, BN = 128, BK = 16;
    __shared__ float As[BK][BM];
    __shared__ float Bs[BK][BN];
    int tid = threadIdx.x;
    int tx = tid & 15, ty = tid >> 4;
    const float* Ab = A + (size_t)blockIdx.x * BM * K;
    const float* Bb = B + (size_t)blockIdx.y * BN * K;
    float acc[8][8];
#pragma unroll
    for (int i = 0; i < 8; i++)
#pragma unroll
        for (int j = 0; j < 8; j++) acc[i][j] = 0.f;

    int lr = tid >> 2;          // 0..63
    int lc = (tid & 3) * 4;     // 0,4,8,12
    for (int k0 = 0; k0 < K; k0 += BK) {
#pragma unroll
        for (int r = 0; r < 2; r++) {
            int row = lr + r * 64;
            float4 v = *(const float4*)(Ab + (size_t)row * K + k0 + lc);
            As[lc + 0][row] = v.x; As[lc + 1][row] = v.y;
            As[lc + 2][row] = v.z; As[lc + 3][row] = v.w;
        }
#pragma unroll
        for (int r = 0; r < 2; r++) {
            int row = lr + r * 64;
            float4 v = *(const float4*)(Bb + (size_t)row * K + k0 + lc);
            Bs[lc + 0][row] = v.x; Bs[lc + 1][row] = v.y;
            Bs[lc + 2][row] = v.z; Bs[lc + 3][row] = v.w;
        }
        __syncthreads();
#pragma unroll
        for (int k = 0; k < BK; k++) {
            float a[8], b[8];
            *(float4*)&a[0] = *(const float4*)&As[k][ty * 8];
            *(float4*)&a[4] = *(const float4*)&As[k][ty * 8 + 4];
            *(float4*)&b[0] = *(const float4*)&Bs[k][tx * 8];
            *(float4*)&b[4] = *(const float4*)&Bs[k][tx * 8 + 4];
#pragma unroll
            for (int i = 0; i < 8; i++)
#pragma unroll
                for (int j = 0; j < 8; j++)
                    acc[i][j] = fmaf(a[i], b[j], acc[i][j]);
        }
        __syncthreads();
    }
#pragma unroll
    for (int i = 0; i < 8; i++) {
        size_t row = (size_t)blockIdx.x * BM + ty * 8 + i;
        float* Cr = C + row * N + blockIdx.y * BN + tx * 8;
#pragma unroll
        for (int j = 0; j < 8; j++) {
            float v = acc[i][j];
            if (EPI == 1) v = fmaxf(v, 0.f);
            Cr[j] = v;
        }
    }
}

// Grouped per-expert GEMM over permuted token rows.
// EPI 2: relu(gval[row] * acc)   (expert gate proj)
// EPI 3: cw[row] * acc           (expert down proj, combine weight applied)
template<int EPI, int GATHER>
__global__ void __launch_bounds__(256) gemm_tn_expert(const float* __restrict__ A,
                                                      const float* __restrict__ Bbase,
                                                      float* __restrict__ C,
                                                      int N, int K, size_t strideB) {
    const int BM = 128, BN = 128, BK = 16;
    int e = blockIdx.z;
    int cnt = g_counts[e];
    int base = g_offsets[e];
    int m0 = blockIdx.x * BM;
    if (m0 >= cnt) return;

    __shared__ float As[BK][BM];
    __shared__ float Bs[BK][BN];
    int tid = threadIdx.x;
    int tx = tid & 15, ty = tid >> 4;
    const float* Bb = Bbase + (size_t)e * strideB + (size_t)blockIdx.y * BN * K;
    float acc[8][8];
#pragma unroll
    for (int i = 0; i < 8; i++)
#pragma unroll
        for (int j = 0; j < 8; j++) acc[i][j] = 0.f;

    int lr = tid >> 2;
    int lc = (tid & 3) * 4;
    // hoist gathered A row indices (fixed across k tiles)
    long arow[2];
#pragma unroll
    for (int r = 0; r < 2; r++) {
        int rowInE = m0 + lr + r * 64;
        if (rowInE < cnt)
            arow[r] = GATHER ? (long)g_perm[base + rowInE] : (long)(base + rowInE);
        else
            arow[r] = -1;
    }

    for (int k0 = 0; k0 < K; k0 += BK) {
#pragma unroll
        for (int r = 0; r < 2; r++) {
            int row = lr + r * 64;
            float4 v = make_float4(0.f, 0.f, 0.f, 0.f);
            if (arow[r] >= 0)
                v = *(const float4*)(A + (size_t)arow[r] * K + k0 + lc);
            As[lc + 0][row] = v.x; As[lc + 1][row] = v.y;
            As[lc + 2][row] = v.z; As[lc + 3][row] = v.w;
        }
#pragma unroll
        for (int r = 0; r < 2; r++) {
            int row = lr + r * 64;
            float4 v = *(const float4*)(Bb + (size_t)row * K + k0 + lc);
            Bs[lc + 0][row] = v.x; Bs[lc + 1][row] = v.y;
            Bs[lc + 2][row] = v.z; Bs[lc + 3][row] = v.w;
        }
        __syncthreads();
#pragma unroll
        for (int k = 0; k < BK; k++) {
            float a[8], b[8];
            *(float4*)&a[0] = *(const float4*)&As[k][ty * 8];
            *(float4*)&a[4] = *(const float4*)&As[k][ty * 8 + 4];
            *(float4*)&b[0] = *(const float4*)&Bs[k][tx * 8];
            *(float4*)&b[4] = *(const float4*)&Bs[k][tx * 8 + 4];
#pragma unroll
            for (int i = 0; i < 8; i++)
#pragma unroll
                for (int j = 0; j < 8; j++)
                    acc[i][j] = fmaf(a[i], b[j], acc[i][j]);
        }
        __syncthreads();
    }
#pragma unroll
    for (int i = 0; i < 8; i++) {
        int rowInE = m0 + ty * 8 + i;
        if (rowInE >= cnt) continue;
        size_t row = (size_t)base + rowInE;
        float scale = (EPI == 2) ? g_gval[row] : g_cw[row];
        float* Cr = C + row * N + blockIdx.y * BN + tx * 8;
#pragma unroll
        for (int j = 0; j < 8; j++) {
            float v = scale * acc[i][j];
            if (EPI == 2) v = fmaxf(v, 0.f);
            Cr[j] = v;
        }
    }
}

// out[t] = yout[slot(t,0)] + yout[slot(t,1)]   (cw already applied)
__global__ void combine_kernel(float* __restrict__ out) {
    int idx = blockIdx.x * blockDim.x + threadIdx.x;  // over T*H/4
    int t = idx / (H_DIM / 4);
    int c = (idx % (H_DIM / 4)) * 4;
    int s0 = g_slot[t * 2], s1 = g_slot[t * 2 + 1];
    float4 a = *(const float4*)&g_yout[(size_t)s0 * H_DIM + c];
    float4 b = *(const float4*)&g_yout[(size_t)s1 * H_DIM + c];
    float4 r = make_float4(a.x + b.x, a.y + b.y, a.z + b.z, a.w + b.w);
    *(float4*)&out[(size_t)t * H_DIM + c] = r;
}

__global__ void aux_kernel(float* __restrict__ out_aux) {
    float imps = 0.f, lds = 0.f;
    float imp[NE], ld[NE];
    for (int e = 0; e < NE; e++) {
        imp[e] = g_importance[e]; ld[e] = (float)g_counts[e];
        imps += imp[e]; lds += ld[e];
    }
    float a = 0.f;
    for (int e = 0; e < NE; e++)
        a += (imp[e] / (imps + 1e-9f)) * (ld[e] / (lds + 1e-9f));
    *out_aux = (float)NE * a;
}

// ---------------- launch -----------------------------------------------------
extern "C" void kernel_launch(void* const* d_in, const int* in_sizes, int n_in,
                              void* d_out, int out_size) {
    const float* x  = (const float*)d_in[0];  // [T, H]
    const float* rw = (const float*)d_in[1];  // [E, H]
    const float* sg = (const float*)d_in[2];  // [HS, H]
    const float* sd = (const float*)d_in[3];  // [H, HS]
    const float* pg = (const float*)d_in[4];  // [E, H]
    const float* gw = (const float*)d_in[5];  // [E, P, H]
    const float* dw = (const float*)d_in[6];  // [E, H, P]

    float* out        = (float*)d_out;
    float* out_logits = out + (size_t)T_TOK * H_DIM;
    float* out_aux    = out_logits + (size_t)T_TOK * NE;

    float *pu, *ph1, *pact, *pyout;
    cudaGetSymbolAddress((void**)&pu, g_u);
    cudaGetSymbolAddress((void**)&ph1, g_h1);
    cudaGetSymbolAddress((void**)&pact, g_act);
    cudaGetSymbolAddress((void**)&pyout, g_yout);

    zero_kernel<<<1, 32>>>();
    router_kernel<<<T_TOK / 8, 256>>>(x, rw, out_logits);
    offsets_kernel<<<1, 1>>>();
    scatter_kernel<<<T_TOK / 256, 256>>>();

    // shared gate: u = relu(x @ sg^T)   [T, HS]
    {
        dim3 g(T_TOK / 128, HS_DIM / 128);
        gemm_tn_plain<1><<<g, 256>>>(x, sg, pu, HS_DIM, H_DIM);
    }
    // shared down: h1 = u @ sd^T        [T, H]
    {
        dim3 g(T_TOK / 128, H_DIM / 128);
        gemm_tn_plain<0><<<g, 256>>>(pu, sd, ph1, H_DIM, HS_DIM);
    }
    pg_kernel<<<T_TOK / 8, 256>>>(ph1, pg);
    gval_kernel<<<TK / 256, 256>>>();

    // expert gate: act[slot] = relu(g * (h1[perm] @ g_w[e]^T))   [TK, P]
    {
        dim3 g(T_TOK / 128, P_DIM / 128, NE);
        gemm_tn_expert<2, 1><<<g, 256>>>(ph1, gw, pact, P_DIM, H_DIM,
                                         (size_t)P_DIM * H_DIM);
    }
    // expert down: yout[slot] = cw * (act[slot] @ d_w[e]^T)      [TK, H]
    {
        dim3 g(T_TOK / 128, H_DIM / 128, NE);
        gemm_tn_expert<3, 0><<<g, 256>>>(pact, dw, pyout, H_DIM, P_DIM,
                                         (size_t)H_DIM * P_DIM);
    }
    combine_kernel<<<(T_TOK * H_DIM / 4) / 256, 256>>>(out);
    aux_kernel<<<1, 1>>>(out_aux);
}

// round 3
// speedup vs baseline: 2.1165x; 2.1165x over previous
#include <cuda_runtime.h>
#include <cuda_bf16.h>
#include <math.h>
#include <stdint.h>

#define T_TOK 8192
#define H_DIM 2048
#define HS_DIM 4096
#define P_DIM 1024
#define NE 8
#define TK (T_TOK*2)

// ======================= PTX helpers (all <= sm_80 features) =================
__device__ __forceinline__ uint32_t smem_u32(const void* p) {
    uint32_t a;
    asm("{ .reg .u64 t; cvta.to.shared.u64 t, %1; cvt.u32.u64 %0, t; }" : "=r"(a) : "l"(p));
    return a;
}
#define CP_ASYNC16(dst, src, sz) \
    asm volatile("cp.async.cg.shared.global [%0], [%1], 16, %2;" \
                 :: "r"(dst), "l"(src), "r"(sz) : "memory")
#define CP_COMMIT() asm volatile("cp.async.commit_group;" ::: "memory")
#define CP_WAIT(n)  asm volatile("cp.async.wait_group %0;" :: "n"(n) : "memory")

#define LDSM4(r0, r1, r2, r3, addr) \
    asm volatile("ldmatrix.sync.aligned.m8n8.x4.shared.b16 {%0,%1,%2,%3}, [%4];" \
                 : "=r"(r0), "=r"(r1), "=r"(r2), "=r"(r3) : "r"(addr))
#define LDSM2(r0, r1, addr) \
    asm volatile("ldmatrix.sync.aligned.m8n8.x2.shared.b16 {%0,%1}, [%2];" \
                 : "=r"(r0), "=r"(r1) : "r"(addr))

#define MMA16816(d, a0, a1, a2, a3, b0, b1) \
    asm volatile("mma.sync.aligned.m16n8k16.row.col.f32.bf16.bf16.f32 " \
                 "{%0,%1,%2,%3}, {%4,%5,%6,%7}, {%8,%9}, {%0,%1,%2,%3};" \
                 : "+f"((d)[0]), "+f"((d)[1]), "+f"((d)[2]), "+f"((d)[3]) \
                 : "r"(a0), "r"(a1), "r"(a2), "r"(a3), "r"(b0), "r"(b1))

// ======================= scratch (device globals) ============================
__device__ __nv_bfloat16 g_xh[(size_t)T_TOK * H_DIM],  g_xl[(size_t)T_TOK * H_DIM];
__device__ __nv_bfloat16 g_sgh[(size_t)HS_DIM * H_DIM], g_sgl[(size_t)HS_DIM * H_DIM];
__device__ __nv_bfloat16 g_sdh[(size_t)H_DIM * HS_DIM], g_sdl[(size_t)H_DIM * HS_DIM];
__device__ __nv_bfloat16 g_uh[(size_t)T_TOK * HS_DIM],  g_ul[(size_t)T_TOK * HS_DIM];
__device__ float         g_h1[(size_t)T_TOK * H_DIM];
__device__ __nv_bfloat16 g_h1h[(size_t)T_TOK * H_DIM],  g_h1l[(size_t)T_TOK * H_DIM];
__device__ __nv_bfloat16 g_gwh[(size_t)NE * P_DIM * H_DIM], g_gwl[(size_t)NE * P_DIM * H_DIM];
__device__ __nv_bfloat16 g_dwh[(size_t)NE * H_DIM * P_DIM], g_dwl[(size_t)NE * H_DIM * P_DIM];
__device__ __nv_bfloat16 g_acth[(size_t)TK * P_DIM],    g_actl[(size_t)TK * P_DIM];
__device__ float         g_yout[(size_t)TK * H_DIM];
__device__ float g_gate[T_TOK * NE];
__device__ int   g_perm[TK];
__device__ int   g_eid[TK];
__device__ float g_cw[TK];
__device__ float g_gval[TK];
__device__ int   g_slot[TK];
__device__ int   g_sel[TK];
__device__ float g_wts[TK];
__device__ int   g_counts[NE];
__device__ int   g_offsets[NE + 1];
__device__ int   g_cursor[NE];
__device__ float g_importance[NE];

// ======================= split fp32 -> bf16 hi/lo ============================
__device__ __forceinline__ void split1(float f, unsigned short& hs, unsigned short& ls) {
    unsigned int b = __float_as_uint(f);
    hs = (unsigned short)(b >> 16);
    float lo = f - __uint_as_float(b & 0xffff0000u);
    ls = __bfloat16_as_ushort(__float2bfloat16_rn(lo));
}

__global__ void split_kernel(const float* __restrict__ s, __nv_bfloat16* __restrict__ h,
                             __nv_bfloat16* __restrict__ l, int n4) {
    int i = blockIdx.x * blockDim.x + threadIdx.x;
    if (i >= n4) return;
    float4 v = ((const float4*)s)[i];
    unsigned short h0, h1, h2, h3, l0, l1, l2, l3;
    split1(v.x, h0, l0); split1(v.y, h1, l1); split1(v.z, h2, l2); split1(v.w, h3, l3);
    ((uint2*)h)[i] = make_uint2((uint32_t)h0 | ((uint32_t)h1 << 16),
                                (uint32_t)h2 | ((uint32_t)h3 << 16));
    ((uint2*)l)[i] = make_uint2((uint32_t)l0 | ((uint32_t)l1 << 16),
                                (uint32_t)l2 | ((uint32_t)l3 << 16));
}

// ======================= small kernels =======================================
__global__ void zero_kernel() {
    int i = threadIdx.x;
    if (i < NE) { g_counts[i] = 0; g_cursor[i] = 0; g_importance[i] = 0.f; }
}

__global__ void router_kernel(const float* __restrict__ x,
                              const float* __restrict__ rw,
                              float* __restrict__ logits_out) {
    __shared__ float s_imp[NE];
    __shared__ int   s_cnt[NE];
    int tid = threadIdx.x;
    if (tid < NE) { s_imp[tid] = 0.f; s_cnt[tid] = 0; }
    __syncthreads();
    int warp = tid >> 5, lane = tid & 31;
    int t = blockIdx.x * 8 + warp;
    float acc[NE];
#pragma unroll
    for (int e = 0; e < NE; e++) acc[e] = 0.f;
    const float* xr = x + (size_t)t * H_DIM;
    for (int i = lane; i < H_DIM; i += 32) {
        float xv = xr[i];
#pragma unroll
        for (int e = 0; e < NE; e++) acc[e] += xv * rw[e * H_DIM + i];
    }
#pragma unroll
    for (int e = 0; e < NE; e++) {
#pragma unroll
        for (int o = 16; o > 0; o >>= 1) acc[e] += __shfl_xor_sync(0xffffffffu, acc[e], o);
    }
    if (lane == 0) {
        float mx = acc[0];
#pragma unroll
        for (int e = 1; e < NE; e++) mx = fmaxf(mx, acc[e]);
        float p[NE]; float s = 0.f;
#pragma unroll
        for (int e = 0; e < NE; e++) { p[e] = expf(acc[e] - mx); s += p[e]; }
        float inv = 1.f / s;
        int i0 = 0; float b0 = -1.f;
#pragma unroll
        for (int e = 0; e < NE; e++) {
            p[e] *= inv;
            logits_out[t * NE + e] = acc[e];
            if (p[e] > b0) { b0 = p[e]; i0 = e; }
        }
        int i1 = 0; float b1 = -1.f;
#pragma unroll
        for (int e = 0; e < NE; e++)
            if (e != i0 && p[e] > b1) { b1 = p[e]; i1 = e; }
        g_sel[t * 2] = i0; g_sel[t * 2 + 1] = i1;
        g_wts[t * 2] = b0; g_wts[t * 2 + 1] = b1;
#pragma unroll
        for (int e = 0; e < NE; e++) atomicAdd(&s_imp[e], p[e]);
        atomicAdd(&s_cnt[i0], 1); atomicAdd(&s_cnt[i1], 1);
    }
    __syncthreads();
    if (tid < NE) {
        atomicAdd(&g_importance[tid], s_imp[tid]);
        atomicAdd(&g_counts[tid], s_cnt[tid]);
    }
}

__global__ void offsets_kernel() {
    int off = 0;
    for (int e = 0; e < NE; e++) { g_offsets[e] = off; g_cursor[e] = off; off += g_counts[e]; }
    g_offsets[NE] = off;
}

__global__ void scatter_kernel() {
    int t = blockIdx.x * blockDim.x + threadIdx.x;
    if (t >= T_TOK) return;
#pragma unroll
    for (int k = 0; k < 2; k++) {
        int e = g_sel[t * 2 + k];
        int pos = atomicAdd(&g_cursor[e], 1);
        g_perm[pos] = t;
        g_cw[pos] = g_wts[t * 2 + k];
        g_eid[pos] = e;
        g_slot[t * 2 + k] = pos;
    }
}

__global__ void pg_kernel(const float* __restrict__ h1,
                          const float* __restrict__ pg) {
    int tid = threadIdx.x;
    int warp = tid >> 5, lane = tid & 31;
    int t = blockIdx.x * 8 + warp;
    float acc[NE];
#pragma unroll
    for (int e = 0; e < NE; e++) acc[e] = 0.f;
    const float* hr = h1 + (size_t)t * H_DIM;
    for (int i = lane; i < H_DIM; i += 32) {
        float hv = hr[i];
#pragma unroll
        for (int e = 0; e < NE; e++) acc[e] += hv * pg[e * H_DIM + i];
    }
#pragma unroll
    for (int e = 0; e < NE; e++) {
#pragma unroll
        for (int o = 16; o > 0; o >>= 1) acc[e] += __shfl_xor_sync(0xffffffffu, acc[e], o);
    }
    if (lane == 0) {
#pragma unroll
        for (int e = 0; e < NE; e++)
            g_gate[t * NE + e] = 1.f / (1.f + expf(-acc[e]));
    }
}

__global__ void gval_kernel() {
    int s = blockIdx.x * blockDim.x + threadIdx.x;
    if (s >= TK) return;
    g_gval[s] = g_gate[g_perm[s] * NE + g_eid[s]];
}

__global__ void combine_kernel(float* __restrict__ out) {
    int idx = blockIdx.x * blockDim.x + threadIdx.x;
    int t = idx / (H_DIM / 4);
    int c = (idx % (H_DIM / 4)) * 4;
    int s0 = g_slot[t * 2], s1 = g_slot[t * 2 + 1];
    float4 a = *(const float4*)&g_yout[(size_t)s0 * H_DIM + c];
    float4 b = *(const float4*)&g_yout[(size_t)s1 * H_DIM + c];
    *(float4*)&out[(size_t)t * H_DIM + c] =
        make_float4(a.x + b.x, a.y + b.y, a.z + b.z, a.w + b.w);
}

__global__ void aux_kernel(float* __restrict__ out_aux) {
    float imps = 0.f, lds = 0.f;
    float imp[NE], ld[NE];
    for (int e = 0; e < NE; e++) {
        imp[e] = g_importance[e]; ld[e] = (float)g_counts[e];
        imps += imp[e]; lds += ld[e];
    }
    float a = 0.f;
    for (int e = 0; e < NE; e++)
        a += (imp[e] / (imps + 1e-9f)) * (ld[e] / (lds + 1e-9f));
    *out_aux = (float)NE * a;
}

// ======================= bf16x3-split HMMA GEMM ==============================
// C[M,N] = A[M,K] @ B[N,K]^T  via  Ah*Bh + Ah*Bl + Al*Bh, fp32 accumulate.
// 128x128 CTA tile, BK=32, 8 warps (2x4), mma.sync m16n8k16 + ldmatrix.
// SMEM rows padded to 80B -> conflict-free ldmatrix without swizzle.
// MODE 0: relu(acc)        -> Oh/Ol splits
// MODE 1: acc              -> Of fp32 + Oh/Ol splits
// MODE 2: relu(gval*acc)   -> Oh/Ol splits  (expert, A rows gathered via perm)
// MODE 3: cw*acc           -> Of fp32       (expert, A rows contiguous slots)
#define BM 128
#define BN 128
#define BK 32
#define ROWB 80                     // padded row stride (bytes) for 64B of data
#define ARR_B (128 * ROWB)          // 10240 per array
#define STAGE_B (4 * ARR_B)         // Ah|Al|Bh|Bl per stage
#define GSMEM (2 * STAGE_B)         // 81920

template<int MODE>
__global__ void __launch_bounds__(256, 1) gemm_mma(
    const __nv_bfloat16* __restrict__ Ah, const __nv_bfloat16* __restrict__ Al,
    const __nv_bfloat16* __restrict__ Bh, const __nv_bfloat16* __restrict__ Bl,
    __nv_bfloat16* __restrict__ Oh, __nv_bfloat16* __restrict__ Ol,
    float* __restrict__ Of, int N, int K, size_t strideB) {
    extern __shared__ char smem[];
    const int tid = threadIdx.x;
    const int wid = tid >> 5, lane = tid & 31;
    const int warp_m = wid & 1;          // 2 warps over M (64 rows each)
    const int warp_n = wid >> 1;         // 4 warps over N (32 cols each)

    int cnt = BM, base = 0;
    const int m0i = blockIdx.x * BM;
    const int n0i = blockIdx.y * BN;
    if (MODE >= 2) {
        int e = blockIdx.z;
        cnt = g_counts[e]; base = g_offsets[e];
        if (m0i >= cnt) return;
        Bh += (size_t)e * strideB;
        Bl += (size_t)e * strideB;
    }

    // ---- gmem->smem load mapping: 2 threads per row, 2x16B each -------------
    const int lr = tid >> 1;             // row 0..127
    const int lc = (tid & 1) * 2;        // chunk 0 or 2 (16B chunks)
    long aRow;
    if (MODE == 2) { int r = m0i + lr; aRow = (r < cnt) ? (long)g_perm[base + r] : -1; }
    else if (MODE == 3) { int r = m0i + lr; aRow = (r < cnt) ? (long)(base + r) : -1; }
    else aRow = (long)(m0i + lr);
    const uint32_t aSz = (aRow >= 0) ? 16u : 0u;
    const size_t aRowC = (size_t)(aRow >= 0 ? aRow : 0);
    const size_t bRow = (size_t)(n0i + lr);

    const uint32_t sb = smem_u32(smem);
    const uint32_t dOff = (uint32_t)lr * ROWB + (uint32_t)lc * 16;

    // ---- ldmatrix lane addresses --------------------------------------------
    // A x4: lanes 0-7 rows m..m+7 @k0 | 8-15 rows m+8..15 @k0 | 16-31 same @k0+8
    const int rA = (lane & 7) + ((lane >> 3) & 1) * 8;
    const uint32_t kcA = (uint32_t)(lane >> 4) * 16;   // 0 or 16 bytes
    uint32_t aoff[4];
#pragma unroll
    for (int mt = 0; mt < 4; mt++)
        aoff[mt] = (uint32_t)(warp_m * 64 + mt * 16 + rA) * ROWB + kcA;
    // B x2: lanes 0-7 rows n..n+7 @k0 | lanes 8-15 rows n..n+7 @k0+8
    const int l2 = lane & 15;
    uint32_t boff[4];
#pragma unroll
    for (int nt = 0; nt < 4; nt++)
        boff[nt] = (uint32_t)(warp_n * 32 + nt * 8 + (l2 & 7)) * ROWB
                 + (uint32_t)(l2 >> 3) * 16;

    float acc[4][4][4];
#pragma unroll
    for (int mt = 0; mt < 4; mt++)
#pragma unroll
        for (int nt = 0; nt < 4; nt++)
#pragma unroll
            for (int q = 0; q < 4; q++) acc[mt][nt][q] = 0.f;

    const int nk = K / BK;

    // prefetch macro body
#define PREFETCH(stage, cIdx) do {                                              \
        const size_t ko = (size_t)(cIdx) * BK + (size_t)lc * 8;                 \
        const uint32_t d0 = sb + (stage) * STAGE_B + dOff;                      \
        CP_ASYNC16(d0,                Ah + aRowC * K + ko,     aSz);            \
        CP_ASYNC16(d0 + 16,           Ah + aRowC * K + ko + 8, aSz);            \
        CP_ASYNC16(d0 + ARR_B,        Al + aRowC * K + ko,     aSz);            \
        CP_ASYNC16(d0 + ARR_B + 16,   Al + aRowC * K + ko + 8, aSz);            \
        CP_ASYNC16(d0 + 2*ARR_B,      Bh + bRow * K + ko,      16u);            \
        CP_ASYNC16(d0 + 2*ARR_B + 16, Bh + bRow * K + ko + 8,  16u);            \
        CP_ASYNC16(d0 + 3*ARR_B,      Bl + bRow * K + ko,      16u);            \
        CP_ASYNC16(d0 + 3*ARR_B + 16, Bl + bRow * K + ko + 8,  16u);            \
    } while (0)

    PREFETCH(0, 0);
    CP_COMMIT();

    for (int c = 0; c < nk; ++c) {
        if (c + 1 < nk) {
            PREFETCH((c + 1) & 1, c + 1);
            CP_COMMIT();
            CP_WAIT(1);
        } else {
            CP_WAIT(0);
        }
        __syncthreads();
        const uint32_t st = sb + (uint32_t)(c & 1) * STAGE_B;
#pragma unroll
        for (int ks = 0; ks < 2; ++ks) {
            const uint32_t kb = (uint32_t)ks * 32;
            uint32_t ah[4][4], al[4][4], bh[4][2], bl[4][2];
#pragma unroll
            for (int mt = 0; mt < 4; mt++) {
                LDSM4(ah[mt][0], ah[mt][1], ah[mt][2], ah[mt][3], st + aoff[mt] + kb);
                LDSM4(al[mt][0], al[mt][1], al[mt][2], al[mt][3], st + ARR_B + aoff[mt] + kb);
            }
#pragma unroll
            for (int nt = 0; nt < 4; nt++) {
                LDSM2(bh[nt][0], bh[nt][1], st + 2 * ARR_B + boff[nt] + kb);
                LDSM2(bl[nt][0], bl[nt][1], st + 3 * ARR_B + boff[nt] + kb);
            }
#pragma unroll
            for (int mt = 0; mt < 4; mt++)
#pragma unroll
                for (int nt = 0; nt < 4; nt++) {
                    MMA16816(acc[mt][nt], ah[mt][0], ah[mt][1], ah[mt][2], ah[mt][3],
                             bh[nt][0], bh[nt][1]);
                    MMA16816(acc[mt][nt], ah[mt][0], ah[mt][1], ah[mt][2], ah[mt][3],
                             bl[nt][0], bl[nt][1]);
                    MMA16816(acc[mt][nt], al[mt][0], al[mt][1], al[mt][2], al[mt][3],
                             bh[nt][0], bh[nt][1]);
                }
        }
        __syncthreads();
    }
#undef PREFETCH

    // ---- epilogue ------------------------------------------------------------
    const int colBase = n0i + warp_n * 32 + (lane & 3) * 2;
#pragma unroll
    for (int mt = 0; mt < 4; mt++) {
#pragma unroll
        for (int h = 0; h < 2; h++) {
            const int rloc = warp_m * 64 + mt * 16 + (lane >> 2) + h * 8;
            const int r = m0i + rloc;
            size_t orow = (size_t)r;
            float scale = 1.f;
            if (MODE >= 2) {
                if (r >= cnt) continue;
                orow = (size_t)base + r;
                scale = (MODE == 2) ? g_gval[orow] : g_cw[orow];
            }
#pragma unroll
            for (int nt = 0; nt < 4; nt++) {
                float v0 = acc[mt][nt][h * 2];
                float v1 = acc[mt][nt][h * 2 + 1];
                if (MODE == 0) { v0 = fmaxf(v0, 0.f); v1 = fmaxf(v1, 0.f); }
                else if (MODE == 2) { v0 = fmaxf(scale * v0, 0.f); v1 = fmaxf(scale * v1, 0.f); }
                else if (MODE == 3) { v0 *= scale; v1 *= scale; }
                const size_t o = orow * N + colBase + nt * 8;
                if (MODE == 1 || MODE == 3)
                    *(float2*)(Of + o) = make_float2(v0, v1);
                if (MODE != 3) {
                    unsigned short h0, l0, h1_, l1_;
                    split1(v0, h0, l0); split1(v1, h1_, l1_);
                    *(uint32_t*)(Oh + o) = (uint32_t)h0 | ((uint32_t)h1_ << 16);
                    *(uint32_t*)(Ol + o) = (uint32_t)l0 | ((uint32_t)l1_ << 16);
                }
            }
        }
    }
}

// ======================= launch ==============================================
extern "C" void kernel_launch(void* const* d_in, const int* in_sizes, int n_in,
                              void* d_out, int out_size) {
    const float* x  = (const float*)d_in[0];  // [T, H]
    const float* rw = (const float*)d_in[1];  // [E, H]
    const float* sg = (const float*)d_in[2];  // [HS, H]
    const float* sd = (const float*)d_in[3];  // [H, HS]
    const float* pg = (const float*)d_in[4];  // [E, H]
    const float* gw = (const float*)d_in[5];  // [E, P, H]
    const float* dw = (const float*)d_in[6];  // [E, H, P]

    float* out        = (float*)d_out;
    float* out_logits = out + (size_t)T_TOK * H_DIM;
    float* out_aux    = out_logits + (size_t)T_TOK * NE;

    __nv_bfloat16 *xh, *xl, *sgh, *sgl, *sdh, *sdl, *uh, *ul, *h1h, *h1l,
                  *gwh, *gwl, *dwh, *dwl, *acth, *actl;
    float *h1, *yout;
    cudaGetSymbolAddress((void**)&xh, g_xh);   cudaGetSymbolAddress((void**)&xl, g_xl);
    cudaGetSymbolAddress((void**)&sgh, g_sgh); cudaGetSymbolAddress((void**)&sgl, g_sgl);
    cudaGetSymbolAddress((void**)&sdh, g_sdh); cudaGetSymbolAddress((void**)&sdl, g_sdl);
    cudaGetSymbolAddress((void**)&uh, g_uh);   cudaGetSymbolAddress((void**)&ul, g_ul);
    cudaGetSymbolAddress((void**)&h1h, g_h1h); cudaGetSymbolAddress((void**)&h1l, g_h1l);
    cudaGetSymbolAddress((void**)&gwh, g_gwh); cudaGetSymbolAddress((void**)&gwl, g_gwl);
    cudaGetSymbolAddress((void**)&dwh, g_dwh); cudaGetSymbolAddress((void**)&dwl, g_dwl);
    cudaGetSymbolAddress((void**)&acth, g_acth); cudaGetSymbolAddress((void**)&actl, g_actl);
    cudaGetSymbolAddress((void**)&h1, g_h1);   cudaGetSymbolAddress((void**)&yout, g_yout);

    cudaFuncSetAttribute(gemm_mma<0>, cudaFuncAttributeMaxDynamicSharedMemorySize, GSMEM);
    cudaFuncSetAttribute(gemm_mma<1>, cudaFuncAttributeMaxDynamicSharedMemorySize, GSMEM);
    cudaFuncSetAttribute(gemm_mma<2>, cudaFuncAttributeMaxDynamicSharedMemorySize, GSMEM);
    cudaFuncSetAttribute(gemm_mma<3>, cudaFuncAttributeMaxDynamicSharedMemorySize, GSMEM);

    // split inputs to bf16 hi/lo
    {
        int n4;
        n4 = T_TOK * H_DIM / 4;      split_kernel<<<(n4 + 255) / 256, 256>>>(x,  xh,  xl,  n4);
        n4 = HS_DIM * H_DIM / 4;     split_kernel<<<(n4 + 255) / 256, 256>>>(sg, sgh, sgl, n4);
        n4 = H_DIM * HS_DIM / 4;     split_kernel<<<(n4 + 255) / 256, 256>>>(sd, sdh, sdl, n4);
        n4 = NE * P_DIM * H_DIM / 4; split_kernel<<<(n4 + 255) / 256, 256>>>(gw, gwh, gwl, n4);
        n4 = NE * H_DIM * P_DIM / 4; split_kernel<<<(n4 + 255) / 256, 256>>>(dw, dwh, dwl, n4);
    }

    zero_kernel<<<1, 32>>>();
    router_kernel<<<T_TOK / 8, 256>>>(x, rw, out_logits);
    offsets_kernel<<<1, 1>>>();
    scatter_kernel<<<T_TOK / 256, 256>>>();

    // u = relu(x @ sg^T)   [T, HS] -> splits
    {
        dim3 g(T_TOK / BM, HS_DIM / BN);
        gemm_mma<0><<<g, 256, GSMEM>>>(xh, xl, sgh, sgl, uh, ul, nullptr,
                                       HS_DIM, H_DIM, 0);
    }
    // h1 = u @ sd^T        [T, H]  -> fp32 + splits
    {
        dim3 g(T_TOK / BM, H_DIM / BN);
        gemm_mma<1><<<g, 256, GSMEM>>>(uh, ul, sdh, sdl, h1h, h1l, h1,
                                       H_DIM, HS_DIM, 0);
    }
    pg_kernel<<<T_TOK / 8, 256>>>(h1, pg);
    gval_kernel<<<TK / 256, 256>>>();

    // act = relu(g * (h1[perm] @ g_w[e]^T))   [TK, P] -> splits
    {
        dim3 g(T_TOK / BM, P_DIM / BN, NE);
        gemm_mma<2><<<g, 256, GSMEM>>>(h1h, h1l, gwh, gwl, acth, actl, nullptr,
                                       P_DIM, H_DIM, (size_t)P_DIM * H_DIM);
    }
    // yout = cw * (act @ d_w[e]^T)            [TK, H] -> fp32
    {
        dim3 g(T_TOK / BM, H_DIM / BN, NE);
        gemm_mma<3><<<g, 256, GSMEM>>>(acth, actl, dwh, dwl, nullptr, nullptr, yout,
                                       H_DIM, P_DIM, (size_t)H_DIM * P_DIM);
    }
    combine_kernel<<<(T_TOK * H_DIM / 4) / 256, 256>>>(out);
    aux_kernel<<<1, 1>>>(out_aux);
}